// round 3
// baseline (speedup 1.0000x reference)
#include <cuda_runtime.h>
#include <cstdint>

#define NT      9
#define SEQ     512
#define BATCH   64
#define EMB     1024
#define CHUNKS  16
#define CHUNK_LEN 32

#define L2E 1.4426950408889634f
#define LN2 0.6931471805599453f

// scratch: per-(batch,chunk) 9x9 semiring matrix products
__device__ float g_M[BATCH * CHUNKS * 81];
// tags dtype flag: 1 = int64, 0 = int32
__device__ int   g_tags64;

__device__ __forceinline__ void ffma2(unsigned long long& acc,
                                      unsigned long long a,
                                      unsigned long long b)
{
    asm("fma.rn.f32x2 %0, %1, %2, %3;" : "=l"(acc) : "l"(a), "l"(b), "l"(acc));
}
__device__ __forceinline__ unsigned long long dup2(float x)
{
    unsigned long long r; asm("mov.b64 %0, {%1,%1};" : "=l"(r) : "f"(x)); return r;
}
__device__ __forceinline__ float fast_ex2(float x)
{
    float r; asm("ex2.approx.ftz.f32 %0, %1;" : "=f"(r) : "f"(x)); return r;
}
__device__ __forceinline__ float fast_lg2(float x)
{
    float r; asm("lg2.approx.ftz.f32 %0, %1;" : "=f"(r) : "f"(x)); return r;
}

// ---------------------------------------------------------------------------
// Kernel 1: emission = log_softmax(embed @ W^T + b)
// 512 blocks x 256 threads. Block covers 64 rows x full K=1024.
// Thread = (rowpair rp 0..31, K-eighth q 0..7): 2 rows x 128 elems.
// W in smem [e][12] (t0..t8 + pad); warp = 32 rowpairs at same q -> all W
// LDS are broadcast. Per element: 3 LDS amortized over 2 rows x 9 tags
// (8 FFMA2 + 2 FFMA). smem W region reused as reduction scratch afterwards.
// ---------------------------------------------------------------------------
__global__ __launch_bounds__(256, 4) void emis3(
    const float* __restrict__ embed,
    const float* __restrict__ W,
    const float* __restrict__ bias,
    const unsigned* __restrict__ tags_words,
    float* __restrict__ out)
{
    __shared__ float sW[EMB * 12];    // 48 KB; later reused as red[64][80]

    const int tid = threadIdx.x;

    if (blockIdx.x == 0) {
        __shared__ int s_any;
        if (tid == 0) s_any = 0;
        __syncthreads();
        int nz = 0;
        for (int qq = tid; qq < 2048; qq += 256)
            nz |= (tags_words[2 * qq + 1] != 0u);
        if (nz) atomicOr(&s_any, 1);
        __syncthreads();
        if (tid == 0) {
            g_tags64 = s_any ? 0 : 1;
            out[0] = 0.0f;               // ll accumulator
        }
    }

    // load W into smem: sW[e*12 + t]
    for (int idx = tid; idx < NT * EMB; idx += 256) {
        int t = idx >> 10;
        int e = idx & 1023;
        sW[e * 12 + t] = W[idx];
    }
    __syncthreads();

    const int q  = tid >> 5;          // K-eighth 0..7
    const int rp = tid & 31;          // rowpair 0..31
    const int row0 = blockIdx.x * 64 + 2 * rp;

    const float* p0 = embed + (size_t)row0 * EMB + q * 128;
    const float* p1 = p0 + EMB;
    const float* wp = sW + (q * 128) * 12;

    unsigned long long a01_0 = 0ull, a23_0 = 0ull, a45_0 = 0ull, a67_0 = 0ull;
    unsigned long long a01_1 = 0ull, a23_1 = 0ull, a45_1 = 0ull, a67_1 = 0ull;
    float a8_0 = 0.0f, a8_1 = 0.0f;

#pragma unroll 2
    for (int e = 0; e < 128; e += 4) {
        float4 x0 = *(const float4*)(p0 + e);
        float4 x1 = *(const float4*)(p1 + e);

#pragma unroll
        for (int u = 0; u < 4; ++u) {
            float xa = (u == 0) ? x0.x : (u == 1) ? x0.y : (u == 2) ? x0.z : x0.w;
            float xb = (u == 0) ? x1.x : (u == 1) ? x1.y : (u == 2) ? x1.z : x1.w;
            const float* we = wp + (e + u) * 12;
            ulonglong2 wA = *(const ulonglong2*)we;        // {w0,w1},{w2,w3}
            ulonglong2 wB = *(const ulonglong2*)(we + 4);  // {w4,w5},{w6,w7}
            float w8 = we[8];
            unsigned long long da = dup2(xa);
            unsigned long long db = dup2(xb);
            ffma2(a01_0, da, wA.x); ffma2(a23_0, da, wA.y);
            ffma2(a45_0, da, wB.x); ffma2(a67_0, da, wB.y);
            a8_0 = fmaf(xa, w8, a8_0);
            ffma2(a01_1, db, wA.x); ffma2(a23_1, db, wA.y);
            ffma2(a45_1, db, wB.x); ffma2(a67_1, db, wB.y);
            a8_1 = fmaf(xb, w8, a8_1);
        }
    }

    __syncthreads();                  // done reading W; reuse sW as scratch
    float* red = sW;                  // red[row][80]: [q*9 + t]

    {
        float2 f;
        float* r0 = &red[(2 * rp) * 80 + q * 9];
        f = *(float2*)&a01_0; r0[0] = f.x; r0[1] = f.y;
        f = *(float2*)&a23_0; r0[2] = f.x; r0[3] = f.y;
        f = *(float2*)&a45_0; r0[4] = f.x; r0[5] = f.y;
        f = *(float2*)&a67_0; r0[6] = f.x; r0[7] = f.y;
        r0[8] = a8_0;
        float* r1 = &red[(2 * rp + 1) * 80 + q * 9];
        f = *(float2*)&a01_1; r1[0] = f.x; r1[1] = f.y;
        f = *(float2*)&a23_1; r1[2] = f.x; r1[3] = f.y;
        f = *(float2*)&a45_1; r1[4] = f.x; r1[5] = f.y;
        f = *(float2*)&a67_1; r1[6] = f.x; r1[7] = f.y;
        r1[8] = a8_1;
    }
    __syncthreads();

    // reduction + log_softmax + store (threads 0..63 = one row each)
    if (tid < 64) {
        const float* rp2 = &red[tid * 80];
        float acc[NT];
#pragma unroll
        for (int t = 0; t < NT; t++) {
            float s = bias[t];
#pragma unroll
            for (int qq = 0; qq < 8; qq++) s += rp2[qq * 9 + t];
            acc[t] = s;
        }

        float mx = acc[0];
#pragma unroll
        for (int t = 1; t < NT; t++) mx = fmaxf(mx, acc[t]);
        float s = 0.0f;
#pragma unroll
        for (int t = 0; t < NT; t++) s += fast_ex2((acc[t] - mx) * L2E);
        float lse = fmaf(fast_lg2(s), LN2, mx);

        float* o = out + 1 + (size_t)(blockIdx.x * 64 + tid) * NT;
#pragma unroll
        for (int t = 0; t < NT; t++) o[t] = acc[t] - lse;
    }
}

// ---------------------------------------------------------------------------
// Kernel 2: chunked forward scan, emissions staged through smem.
// Row i of the running log-semiring product depends only on row i ->
// independent 9-lane row-scans via warp shfl, no cross-row sync.
// exp-trans factorization: lse_k(v_k + T[k][j]) =
//   r + LN2*log2( sum_k 2^{(v_k-r)*L2E} * E2[k][j] ),  E2 = 2^{T*L2E}.
// block = 96 threads = 3 warps; warp handles 3 rows of one (b,chunk).
// ---------------------------------------------------------------------------
__global__ __launch_bounds__(96) void crf_chunks3(
    const float* __restrict__ outbuf,   // d_out; emission at +1
    const int*   __restrict__ mask,
    const float* __restrict__ trans)
{
    const float* emis = outbuf + 1;
    const int c = blockIdx.x, b = blockIdx.y;
    const int tid  = threadIdx.x;
    const int w    = tid >> 5;
    const int lane = tid & 31;

    const int t0 = 1 + c * CHUNK_LEN;
    const int t1 = min(SEQ, t0 + CHUNK_LEN);
    const int n  = t1 - t0;

    __shared__ float sEm[CHUNK_LEN * NT + 4];
    __shared__ int   sMk[CHUNK_LEN];
    __shared__ float sTr[81];

    const float* em_b = emis + (size_t)b * SEQ * NT + (size_t)t0 * NT;
    const int*   mk   = mask + b * SEQ + t0;

    for (int idx = tid; idx < n * NT; idx += 96) sEm[idx] = em_b[idx];
    for (int idx = tid; idx < n;      idx += 96) sMk[idx] = mk[idx];
    if (tid < 81) sTr[tid] = trans[tid];
    __syncthreads();

    int g = lane / 9; if (g > 2) g = 2;          // lanes 27..31 mirror group 2
    const int j = lane % 9;
    const int i = w * 3 + g;
    const int rowbase = g * 9;

    float E2[9];
#pragma unroll
    for (int k = 0; k < 9; k++) E2[k] = fast_ex2(sTr[k * 9 + j] * L2E);
    const float tij = sTr[i * 9 + j];

    float v = (j == i) ? 0.0f : -1e30f;          // identity row
    bool started = false;

    for (int t = 0; t < n; ++t) {
        const int   m  = sMk[t];
        const float ev = sEm[t * NT + j];
        if (m) {
            if (!started) {
                v = tij + ev;                    // first active step: M = A_t
                started = true;
            } else {
                float r = __shfl_sync(0xffffffffu, v, rowbase);
                float e = fast_ex2((v - r) * L2E);
                float s = 0.0f;
#pragma unroll
                for (int k = 0; k < 9; k++)
                    s = fmaf(__shfl_sync(0xffffffffu, e, rowbase + k), E2[k], s);
                v = fmaf(fast_lg2(s), LN2, r) + ev;
            }
        }
    }

    if (lane < 27) g_M[(b * CHUNKS + c) * 81 + i * 9 + j] = v;
}

// ---------------------------------------------------------------------------
// Kernel 3: per-batch numerator + chunk-combine + denominator + atomicAdd ll.
// All 16 chunk matrices preloaded to smem (latency hidden by numerator loop).
// ---------------------------------------------------------------------------
__global__ __launch_bounds__(128) void crf_final(
    float* __restrict__ outbuf,
    const void* __restrict__ tags,
    const int*  __restrict__ mask,
    const float* __restrict__ startT,
    const float* __restrict__ endT,
    const float* __restrict__ trans)
{
    const float* emis = outbuf + 1;
    const int b = blockIdx.x;
    const int tid = threadIdx.x;
    const float* em_b = emis + (size_t)b * SEQ * NT;
    const long long* t64 = (const long long*)tags;
    const int*       t32 = (const int*)tags;
    const int is64 = g_tags64;

    __shared__ float sM[CHUNKS * 81];
    __shared__ float redf[128];
    __shared__ int   redi[128];
    __shared__ float s_num;

    // preload all chunk matrices
    for (int idx = tid; idx < CHUNKS * 81; idx += 128)
        sM[idx] = g_M[b * (CHUNKS * 81) + idx];

    // numerator (parallel over s) + mask count
    float acc = 0.0f;
    int   msum = 0;
    for (int s = tid; s < SEQ; s += 128) {
        int m = mask[b * SEQ + s];
        msum += m;
        if (s >= 1) {
            int tp  = is64 ? (int)t64[b * SEQ + s - 1] : t32[b * SEQ + s - 1];
            int tcu = is64 ? (int)t64[b * SEQ + s]     : t32[b * SEQ + s];
            acc += (float)m * (trans[tp * 9 + tcu] + em_b[s * NT + tcu]);
        }
    }
    redf[tid] = acc; redi[tid] = msum;
    __syncthreads();
    for (int o = 64; o > 0; o >>= 1) {
        if (tid < o) { redf[tid] += redf[tid + o]; redi[tid] += redi[tid + o]; }
        __syncthreads();
    }
    if (tid == 0) {
        int tg0  = is64 ? (int)t64[b * SEQ] : t32[b * SEQ];
        int last = redi[0] - 1;
        int tl   = is64 ? (int)t64[b * SEQ + last] : t32[b * SEQ + last];
        s_num = redf[0] + startT[tg0] + em_b[tg0] + endT[tl];
    }
    __syncthreads();

    // combine chunk matrices (warp 0, lanes 0..8 hold the score vector)
    if (tid < 32) {
        const int j = tid;
        float v = (j < 9) ? (startT[j] + em_b[j]) : -1e30f;
        for (int c = 0; c < CHUNKS; c++) {
            const float* Mc = sM + c * 81;
            float vals[9];
#pragma unroll
            for (int i2 = 0; i2 < 9; i2++) {
                float sv = __shfl_sync(0xffffffffu, v, i2);
                vals[i2] = sv + ((j < 9) ? Mc[i2 * 9 + j] : 0.0f);
            }
            float nv = -1e30f;
            if (j < 9) {
                float mx = vals[0];
#pragma unroll
                for (int i2 = 1; i2 < 9; i2++) mx = fmaxf(mx, vals[i2]);
                float s = 0.0f;
#pragma unroll
                for (int i2 = 0; i2 < 9; i2++) s += fast_ex2((vals[i2] - mx) * L2E);
                nv = fmaf(fast_lg2(s), LN2, mx);
            }
            v = nv;
        }
        // denominator = logsumexp(v + end)
        float x = (j < 9) ? v + endT[j] : -1e30f;
        float mx = x;
#pragma unroll
        for (int o = 16; o > 0; o >>= 1) mx = fmaxf(mx, __shfl_xor_sync(0xffffffffu, mx, o));
        float e = (j < 9) ? fast_ex2((x - mx) * L2E) : 0.0f;
#pragma unroll
        for (int o = 16; o > 0; o >>= 1) e += __shfl_xor_sync(0xffffffffu, e, o);
        if (tid == 0) {
            float den = fmaf(fast_lg2(e), LN2, mx);
            atomicAdd(outbuf, s_num - den);
        }
    }
}

// ---------------------------------------------------------------------------
extern "C" void kernel_launch(void* const* d_in, const int* in_sizes, int n_in,
                              void* d_out, int out_size)
{
    const float* embed  = (const float*)d_in[0];
    const void*  tags   = d_in[1];
    const int*   mask   = (const int*)d_in[2];
    const float* W      = (const float*)d_in[3];
    const float* bias   = (const float*)d_in[4];
    const float* startT = (const float*)d_in[5];
    const float* endT   = (const float*)d_in[6];
    const float* trans  = (const float*)d_in[7];
    float* out = (float*)d_out;

    emis3<<<(BATCH * SEQ) / 64, 256>>>(embed, W, bias,
                                       (const unsigned*)tags, out);
    dim3 g2(CHUNKS, BATCH);
    crf_chunks3<<<g2, 96>>>(out, mask, trans);
    crf_final<<<BATCH, 128>>>(out, tags, mask, startT, endT, trans);
}

// round 4
// speedup vs baseline: 2.4539x; 2.4539x over previous
#include <cuda_runtime.h>
#include <cstdint>

#define NT      9
#define SEQ     512
#define BATCH   64
#define EMB     1024
#define CHUNKS  16
#define CHUNK_LEN 32

#define L2E 1.4426950408889634f
#define LN2 0.6931471805599453f

// scratch: per-(batch,chunk) 9x9 semiring matrix products
__device__ float g_M[BATCH * CHUNKS * 81];
// tags dtype flag: 1 = int64, 0 = int32
__device__ int   g_tags64;

__device__ __forceinline__ void ffma2(unsigned long long& acc,
                                      unsigned long long a,
                                      unsigned long long b)
{
    asm("fma.rn.f32x2 %0, %1, %2, %3;" : "=l"(acc) : "l"(a), "l"(b), "l"(acc));
}
__device__ __forceinline__ unsigned long long dup2(float x)
{
    unsigned long long r; asm("mov.b64 %0, {%1,%1};" : "=l"(r) : "f"(x)); return r;
}
__device__ __forceinline__ float fast_ex2(float x)
{
    float r; asm("ex2.approx.ftz.f32 %0, %1;" : "=f"(r) : "f"(x)); return r;
}
__device__ __forceinline__ float fast_lg2(float x)
{
    float r; asm("lg2.approx.ftz.f32 %0, %1;" : "=f"(r) : "f"(x)); return r;
}

// ---------------------------------------------------------------------------
// Kernel 1: emission = log_softmax(embed @ W^T + b)
// grid 1024, block 128 = 32 rows x 4 K-quarters. K in 16 tiles of 64 cols.
// Tiles staged COALESCED into smem (pad 68 -> conflict-free LDS.128);
// next tile prefetched into registers during compute. W tile in smem,
// [e][12] pair layout, warp-broadcast reads (warp = 32 rows at same q).
// ---------------------------------------------------------------------------
__global__ __launch_bounds__(128) void emis6(
    const float* __restrict__ embed,
    const float* __restrict__ W,
    const float* __restrict__ bias,
    const unsigned* __restrict__ tags_words,
    float* __restrict__ out)
{
    __shared__ float sE[32 * 68];    // 8.5 KB  (reused as red[32][37] at end)
    __shared__ float sWt[64 * 12];   // 3 KB

    const int tid = threadIdx.x;

    if (blockIdx.x == 0) {
        __shared__ int s_any;
        if (tid == 0) s_any = 0;
        __syncthreads();
        int nz = 0;
        for (int qq = tid; qq < 2048; qq += 128)
            nz |= (tags_words[2 * qq + 1] != 0u);
        if (nz) atomicOr(&s_any, 1);
        __syncthreads();
        if (tid == 0) {
            g_tags64 = s_any ? 0 : 1;
            out[0] = 0.0f;               // ll accumulator
        }
    }

    const int q = tid >> 5;          // K-quarter 0..3 (warp id)
    const int r = tid & 31;          // row within block (lane)
    const int rowBase = blockIdx.x * 32;

    // -------- prefetch tile 0 --------
    float4 pe[4];
    float  pw[5];
    {
        const float* gsrc = embed + (size_t)rowBase * EMB;  // tile 0 col offset 0
#pragma unroll
        for (int it = 0; it < 4; ++it) {
            int idx = it * 128 + tid;
            int r2 = idx >> 4, cc = (idx & 15) * 4;
            pe[it] = *(const float4*)(gsrc + (size_t)r2 * EMB + cc);
        }
#pragma unroll
        for (int it = 0; it < 5; ++it) {
            int idx = it * 128 + tid;
            if (idx < 576) {
                int t = idx >> 6, e = idx & 63;
                pw[it] = W[t * EMB + e];
            }
        }
    }

    unsigned long long a01 = 0ull, a23 = 0ull, a45 = 0ull, a67 = 0ull;
    float a8 = 0.0f;

    for (int tile = 0; tile < 16; ++tile) {
        __syncthreads();             // previous compute done reading smem
        // store prefetched tile
#pragma unroll
        for (int it = 0; it < 4; ++it) {
            int idx = it * 128 + tid;
            int r2 = idx >> 4, cc = (idx & 15) * 4;
            *(float4*)&sE[r2 * 68 + cc] = pe[it];
        }
#pragma unroll
        for (int it = 0; it < 5; ++it) {
            int idx = it * 128 + tid;
            if (idx < 576) {
                int t = idx >> 6, e = idx & 63;
                sWt[e * 12 + t] = pw[it];
            }
        }
        __syncthreads();             // tile ready

        // prefetch next tile while computing this one
        if (tile < 15) {
            const float* gsrc = embed + (size_t)rowBase * EMB + (tile + 1) * 64;
#pragma unroll
            for (int it = 0; it < 4; ++it) {
                int idx = it * 128 + tid;
                int r2 = idx >> 4, cc = (idx & 15) * 4;
                pe[it] = *(const float4*)(gsrc + (size_t)r2 * EMB + cc);
            }
#pragma unroll
            for (int it = 0; it < 5; ++it) {
                int idx = it * 128 + tid;
                if (idx < 576) {
                    int t = idx >> 6, e = idx & 63;
                    pw[it] = W[t * EMB + (tile + 1) * 64 + e];
                }
            }
        }

        // compute: 16 cols of this tile (quarter q)
        const float* xr = &sE[r * 68 + q * 16];
        const float* wq = &sWt[(q * 16) * 12];
#pragma unroll
        for (int e4 = 0; e4 < 16; e4 += 4) {
            float4 x = *(const float4*)(xr + e4);
#pragma unroll
            for (int u = 0; u < 4; ++u) {
                float xs = (u == 0) ? x.x : (u == 1) ? x.y : (u == 2) ? x.z : x.w;
                const float* we = wq + (e4 + u) * 12;
                ulonglong2 wA = *(const ulonglong2*)we;        // {w0,w1},{w2,w3}
                ulonglong2 wB = *(const ulonglong2*)(we + 4);  // {w4,w5},{w6,w7}
                float w8 = we[8];
                unsigned long long dx = dup2(xs);
                ffma2(a01, dx, wA.x); ffma2(a23, dx, wA.y);
                ffma2(a45, dx, wB.x); ffma2(a67, dx, wB.y);
                a8 = fmaf(xs, w8, a8);
            }
        }
    }

    // -------- reduction across quarters + log_softmax --------
    __syncthreads();                 // done with sE as tile buffer
    float* red = sE;                 // red[r][37]
    {
        float2 f;
        float* rp = &red[r * 37 + q * 9];
        f = *(float2*)&a01; rp[0] = f.x; rp[1] = f.y;
        f = *(float2*)&a23; rp[2] = f.x; rp[3] = f.y;
        f = *(float2*)&a45; rp[4] = f.x; rp[5] = f.y;
        f = *(float2*)&a67; rp[6] = f.x; rp[7] = f.y;
        rp[8] = a8;
    }
    __syncthreads();

    if (tid < 32) {
        const float* rp = &red[tid * 37];
        float acc[NT];
#pragma unroll
        for (int t = 0; t < NT; t++)
            acc[t] = rp[t] + rp[9 + t] + rp[18 + t] + rp[27 + t] + bias[t];

        float mx = acc[0];
#pragma unroll
        for (int t = 1; t < NT; t++) mx = fmaxf(mx, acc[t]);
        float s = 0.0f;
#pragma unroll
        for (int t = 0; t < NT; t++) s += fast_ex2((acc[t] - mx) * L2E);
        float lse = fmaf(fast_lg2(s), LN2, mx);

        float* o = out + 1 + (size_t)(rowBase + tid) * NT;
#pragma unroll
        for (int t = 0; t < NT; t++) o[t] = acc[t] - lse;
    }
}

// ---------------------------------------------------------------------------
// Kernel 2: chunked forward scan, emissions staged through smem.
// Row i of the running log-semiring product depends only on row i ->
// independent 9-lane row-scans via warp shfl. exp-trans factorization.
// block = 96 threads = 3 warps; warp handles 3 rows of one (b,chunk).
// ---------------------------------------------------------------------------
__global__ __launch_bounds__(96) void crf_chunks3(
    const float* __restrict__ outbuf,   // d_out; emission at +1
    const int*   __restrict__ mask,
    const float* __restrict__ trans)
{
    const float* emis = outbuf + 1;
    const int c = blockIdx.x, b = blockIdx.y;
    const int tid  = threadIdx.x;
    const int w    = tid >> 5;
    const int lane = tid & 31;

    const int t0 = 1 + c * CHUNK_LEN;
    const int t1 = min(SEQ, t0 + CHUNK_LEN);
    const int n  = t1 - t0;

    __shared__ float sEm[CHUNK_LEN * NT + 4];
    __shared__ int   sMk[CHUNK_LEN];
    __shared__ float sTr[81];

    const float* em_b = emis + (size_t)b * SEQ * NT + (size_t)t0 * NT;
    const int*   mk   = mask + b * SEQ + t0;

    for (int idx = tid; idx < n * NT; idx += 96) sEm[idx] = em_b[idx];
    for (int idx = tid; idx < n;      idx += 96) sMk[idx] = mk[idx];
    if (tid < 81) sTr[tid] = trans[tid];
    __syncthreads();

    int g = lane / 9; if (g > 2) g = 2;          // lanes 27..31 mirror group 2
    const int j = lane % 9;
    const int i = w * 3 + g;
    const int rowbase = g * 9;

    float E2[9];
#pragma unroll
    for (int k = 0; k < 9; k++) E2[k] = fast_ex2(sTr[k * 9 + j] * L2E);
    const float tij = sTr[i * 9 + j];

    float v = (j == i) ? 0.0f : -1e30f;          // identity row
    bool started = false;

    for (int t = 0; t < n; ++t) {
        const int   m  = sMk[t];
        const float ev = sEm[t * NT + j];
        if (m) {
            if (!started) {
                v = tij + ev;                    // first active step: M = A_t
                started = true;
            } else {
                float r = __shfl_sync(0xffffffffu, v, rowbase);
                float e = fast_ex2((v - r) * L2E);
                float s = 0.0f;
#pragma unroll
                for (int k = 0; k < 9; k++)
                    s = fmaf(__shfl_sync(0xffffffffu, e, rowbase + k), E2[k], s);
                v = fmaf(fast_lg2(s), LN2, r) + ev;
            }
        }
    }

    if (lane < 27) g_M[(b * CHUNKS + c) * 81 + i * 9 + j] = v;
}

// ---------------------------------------------------------------------------
// Kernel 3: per-batch numerator + chunk-combine + denominator + atomicAdd ll.
// ---------------------------------------------------------------------------
__global__ __launch_bounds__(128) void crf_final(
    float* __restrict__ outbuf,
    const void* __restrict__ tags,
    const int*  __restrict__ mask,
    const float* __restrict__ startT,
    const float* __restrict__ endT,
    const float* __restrict__ trans)
{
    const float* emis = outbuf + 1;
    const int b = blockIdx.x;
    const int tid = threadIdx.x;
    const float* em_b = emis + (size_t)b * SEQ * NT;
    const long long* t64 = (const long long*)tags;
    const int*       t32 = (const int*)tags;
    const int is64 = g_tags64;

    __shared__ float sM[CHUNKS * 81];
    __shared__ float redf[128];
    __shared__ int   redi[128];
    __shared__ float s_num;

    // preload all chunk matrices (latency hidden by numerator loop)
    for (int idx = tid; idx < CHUNKS * 81; idx += 128)
        sM[idx] = g_M[b * (CHUNKS * 81) + idx];

    // numerator (parallel over s) + mask count
    float acc = 0.0f;
    int   msum = 0;
    for (int s = tid; s < SEQ; s += 128) {
        int m = mask[b * SEQ + s];
        msum += m;
        if (s >= 1) {
            int tp  = is64 ? (int)t64[b * SEQ + s - 1] : t32[b * SEQ + s - 1];
            int tcu = is64 ? (int)t64[b * SEQ + s]     : t32[b * SEQ + s];
            acc += (float)m * (trans[tp * 9 + tcu] + em_b[s * NT + tcu]);
        }
    }
    redf[tid] = acc; redi[tid] = msum;
    __syncthreads();
    for (int o = 64; o > 0; o >>= 1) {
        if (tid < o) { redf[tid] += redf[tid + o]; redi[tid] += redi[tid + o]; }
        __syncthreads();
    }
    if (tid == 0) {
        int tg0  = is64 ? (int)t64[b * SEQ] : t32[b * SEQ];
        int last = redi[0] - 1;
        int tl   = is64 ? (int)t64[b * SEQ + last] : t32[b * SEQ + last];
        s_num = redf[0] + startT[tg0] + em_b[tg0] + endT[tl];
    }
    __syncthreads();

    // combine chunk matrices (warp 0, lanes 0..8 hold the score vector)
    if (tid < 32) {
        const int j = tid;
        float v = (j < 9) ? (startT[j] + em_b[j]) : -1e30f;
        for (int c = 0; c < CHUNKS; c++) {
            const float* Mc = sM + c * 81;
            float vals[9];
#pragma unroll
            for (int i2 = 0; i2 < 9; i2++) {
                float sv = __shfl_sync(0xffffffffu, v, i2);
                vals[i2] = sv + ((j < 9) ? Mc[i2 * 9 + j] : 0.0f);
            }
            float nv = -1e30f;
            if (j < 9) {
                float mx = vals[0];
#pragma unroll
                for (int i2 = 1; i2 < 9; i2++) mx = fmaxf(mx, vals[i2]);
                float s = 0.0f;
#pragma unroll
                for (int i2 = 0; i2 < 9; i2++) s += fast_ex2((vals[i2] - mx) * L2E);
                nv = fmaf(fast_lg2(s), LN2, mx);
            }
            v = nv;
        }
        // denominator = logsumexp(v + end)
        float x = (j < 9) ? v + endT[j] : -1e30f;
        float mx = x;
#pragma unroll
        for (int o = 16; o > 0; o >>= 1) mx = fmaxf(mx, __shfl_xor_sync(0xffffffffu, mx, o));
        float e = (j < 9) ? fast_ex2((x - mx) * L2E) : 0.0f;
#pragma unroll
        for (int o = 16; o > 0; o >>= 1) e += __shfl_xor_sync(0xffffffffu, e, o);
        if (tid == 0) {
            float den = fmaf(fast_lg2(e), LN2, mx);
            atomicAdd(outbuf, s_num - den);
        }
    }
}

// ---------------------------------------------------------------------------
extern "C" void kernel_launch(void* const* d_in, const int* in_sizes, int n_in,
                              void* d_out, int out_size)
{
    const float* embed  = (const float*)d_in[0];
    const void*  tags   = d_in[1];
    const int*   mask   = (const int*)d_in[2];
    const float* W      = (const float*)d_in[3];
    const float* bias   = (const float*)d_in[4];
    const float* startT = (const float*)d_in[5];
    const float* endT   = (const float*)d_in[6];
    const float* trans  = (const float*)d_in[7];
    float* out = (float*)d_out;

    emis6<<<(BATCH * SEQ) / 32, 128>>>(embed, W, bias,
                                       (const unsigned*)tags, out);
    dim3 g2(CHUNKS, BATCH);
    crf_chunks3<<<g2, 96>>>(out, mask, trans);
    crf_final<<<BATCH, 128>>>(out, tags, mask, startT, endT, trans);
}